// round 1
// baseline (speedup 1.0000x reference)
#include <cuda_runtime.h>
#include <math.h>

#define B_ 4
#define L_ 2048
#define C_ 1024
#define H_ 16
#define D_ 64
#define M_ (B_ * L_)   // 8192 rows

// Scratch buffers (static device globals; no runtime allocation allowed)
__device__ float g_qkv[(size_t)M_ * 3 * C_];   // [8192, 3072]
__device__ float g_h[(size_t)M_ * C_];         // [8192, 1024]

// ---------------------------------------------------------------------------
// SGEMM: C[M,N] = A[M,K] @ B[K,N] + bias[N]   (all row-major, fp32)
// 128x128 tile, BK=8, 256 threads, 8x8 micro-tile per thread.
// Assumes M%128==0, N%128==0, K%8==0 (true for all our shapes).
// ---------------------------------------------------------------------------
__global__ __launch_bounds__(256) void sgemm_bias_kernel(
    const float* __restrict__ A, const float* __restrict__ Bm,
    const float* __restrict__ bias, float* __restrict__ Cm,
    int M, int N, int K)
{
    __shared__ float As[8][128];
    __shared__ float Bs[8][128];

    const int tid = threadIdx.x;
    const int tx = tid & 15;          // 0..15 -> output cols
    const int ty = tid >> 4;          // 0..15 -> output rows
    const int row0 = blockIdx.y * 128;
    const int col0 = blockIdx.x * 128;

    // loader indices
    const int a_row = tid >> 1;            // 0..127
    const int a_col = (tid & 1) * 4;       // 0 or 4
    const int b_row = tid >> 5;            // 0..7
    const int b_col = (tid & 31) * 4;      // 0..124

    float acc[8][8];
#pragma unroll
    for (int i = 0; i < 8; i++)
#pragma unroll
        for (int j = 0; j < 8; j++) acc[i][j] = 0.0f;

    for (int k0 = 0; k0 < K; k0 += 8) {
        // Load A tile (transposed into As[k][m])
        float4 av = *(const float4*)(A + (size_t)(row0 + a_row) * K + k0 + a_col);
        As[a_col + 0][a_row] = av.x;
        As[a_col + 1][a_row] = av.y;
        As[a_col + 2][a_row] = av.z;
        As[a_col + 3][a_row] = av.w;
        // Load B tile
        float4 bv = *(const float4*)(Bm + (size_t)(k0 + b_row) * N + col0 + b_col);
        *(float4*)&Bs[b_row][b_col] = bv;
        __syncthreads();

#pragma unroll
        for (int kk = 0; kk < 8; kk++) {
            float a[8], b[8];
            *(float4*)&a[0] = *(const float4*)&As[kk][ty * 8];
            *(float4*)&a[4] = *(const float4*)&As[kk][ty * 8 + 4];
            *(float4*)&b[0] = *(const float4*)&Bs[kk][tx * 8];
            *(float4*)&b[4] = *(const float4*)&Bs[kk][tx * 8 + 4];
#pragma unroll
            for (int i = 0; i < 8; i++)
#pragma unroll
                for (int j = 0; j < 8; j++)
                    acc[i][j] += a[i] * b[j];
        }
        __syncthreads();
    }

#pragma unroll
    for (int i = 0; i < 8; i++) {
        const int r = row0 + ty * 8 + i;
#pragma unroll
        for (int j = 0; j < 8; j += 4) {
            const int c = col0 + tx * 8 + j;
            float4 v;
            v.x = acc[i][j + 0] + bias[c + 0];
            v.y = acc[i][j + 1] + bias[c + 1];
            v.z = acc[i][j + 2] + bias[c + 2];
            v.w = acc[i][j + 3] + bias[c + 3];
            *(float4*)(Cm + (size_t)r * N + c) = v;
        }
    }
}

// ---------------------------------------------------------------------------
// Per-head RMS norm on Q and K slices of qkv, in place.
// One warp per (row, part, head) segment of 64 floats.
// norm: t / max(||t||, 1e-12) * gamma * sqrt(D)
// ---------------------------------------------------------------------------
__global__ __launch_bounds__(256) void rmsnorm_kernel(
    float* __restrict__ qkv,
    const float* __restrict__ q_gamma, const float* __restrict__ k_gamma)
{
    const int warp = threadIdx.x >> 5;
    const int lane = threadIdx.x & 31;
    const int seg = blockIdx.x * 8 + warp;   // 0 .. M_*2*H_-1

    const int head = seg % H_;
    const int part = (seg / H_) & 1;         // 0 = q, 1 = k
    const int row  = seg / (H_ * 2);

    float* ptr = qkv + ((size_t)row * 3 + part) * C_ + head * D_;
    float2 v = *(float2*)(ptr + lane * 2);
    float ss = v.x * v.x + v.y * v.y;
#pragma unroll
    for (int m = 16; m > 0; m >>= 1) ss += __shfl_xor_sync(0xffffffffu, ss, m);

    const float n = sqrtf(ss);
    const float scale = 8.0f / fmaxf(n, 1e-12f);   // sqrt(D)=8
    const float* gamma = part ? k_gamma : q_gamma;
    float2 g = *(const float2*)(gamma + head * D_ + lane * 2);
    v.x *= scale * g.x;
    v.y *= scale * g.y;
    *(float2*)(ptr + lane * 2) = v;
}

// ---------------------------------------------------------------------------
// Flash-style attention. One CTA = (b, h, 64-row Q tile).
// 256 threads: 16x16 grid, each thread owns a 4x4 patch of the 64x64 score
// tile and a 4(row)x4(dim) patch of the output accumulator.
// Smem: Qt/Kt transposed [dim][row] pitch 68, Vs [key][dim] pitch 68,
//       Ps [row][key] pitch 68.  Total = 4*64*68*4 = 69632 B (dynamic).
// ---------------------------------------------------------------------------
#define AP 68  // smem pitch (floats), multiple of 4 for float4 alignment

__global__ __launch_bounds__(256) void attn_kernel(
    const float* __restrict__ qkv, float* __restrict__ hout)
{
    extern __shared__ float sm[];
    float (*Qt)[AP] = (float(*)[AP])(sm);
    float (*Kt)[AP] = (float(*)[AP])(sm + 64 * AP);
    float (*Vs)[AP] = (float(*)[AP])(sm + 2 * 64 * AP);
    float (*Ps)[AP] = (float(*)[AP])(sm + 3 * 64 * AP);

    const int tid = threadIdx.x;
    const int tx = tid & 15;
    const int ty = tid >> 4;
    const int b = blockIdx.z;
    const int h = blockIdx.y;
    const int l0 = blockIdx.x * 64;

    // loader mapping: thread -> (row lr, 16-wide col chunk lc)
    const int lr = tid >> 2;
    const int lc = (tid & 3) * 16;

    // Load Q tile transposed: Qt[d][r]
    {
        const float* src = qkv + (((size_t)(b * L_ + l0 + lr) * 3 + 0) * C_) + h * D_;
#pragma unroll
        for (int u = 0; u < 4; u++) {
            float4 t = *(const float4*)(src + lc + u * 4);
            Qt[lc + u * 4 + 0][lr] = t.x;
            Qt[lc + u * 4 + 1][lr] = t.y;
            Qt[lc + u * 4 + 2][lr] = t.z;
            Qt[lc + u * 4 + 3][lr] = t.w;
        }
    }

    float m[4], lsum[4], O[4][4];
#pragma unroll
    for (int i = 0; i < 4; i++) {
        m[i] = -1e30f; lsum[i] = 0.0f;
#pragma unroll
        for (int j = 0; j < 4; j++) O[i][j] = 0.0f;
    }

    const float scale = 0.125f;   // 1/sqrt(64)

    for (int n0 = 0; n0 < L_; n0 += 64) {
        __syncthreads();   // protect Kt/Vs/Ps from previous iteration readers

        // Load K (transposed) and V tiles
        {
            const float* ksrc = qkv + (((size_t)(b * L_ + n0 + lr) * 3 + 1) * C_) + h * D_;
            const float* vsrc = qkv + (((size_t)(b * L_ + n0 + lr) * 3 + 2) * C_) + h * D_;
#pragma unroll
            for (int u = 0; u < 4; u++) {
                float4 t = *(const float4*)(ksrc + lc + u * 4);
                Kt[lc + u * 4 + 0][lr] = t.x;
                Kt[lc + u * 4 + 1][lr] = t.y;
                Kt[lc + u * 4 + 2][lr] = t.z;
                Kt[lc + u * 4 + 3][lr] = t.w;
                *(float4*)&Vs[lr][lc + u * 4] = *(const float4*)(vsrc + lc + u * 4);
            }
        }
        __syncthreads();

        // S = scale * Q K^T  (4x4 per thread)
        float s[4][4];
#pragma unroll
        for (int i = 0; i < 4; i++)
#pragma unroll
            for (int j = 0; j < 4; j++) s[i][j] = 0.0f;

#pragma unroll 8
        for (int k = 0; k < 64; k++) {
            float a[4], bq[4];
            *(float4*)a  = *(const float4*)&Qt[k][ty * 4];
            *(float4*)bq = *(const float4*)&Kt[k][tx * 4];
#pragma unroll
            for (int i = 0; i < 4; i++)
#pragma unroll
                for (int j = 0; j < 4; j++)
                    s[i][j] += a[i] * bq[j];
        }

        // online softmax, per row group (16 lanes share the 4 rows of ty)
#pragma unroll
        for (int i = 0; i < 4; i++) {
            float rmax = s[i][0];
            rmax = fmaxf(rmax, s[i][1]);
            rmax = fmaxf(rmax, s[i][2]);
            rmax = fmaxf(rmax, s[i][3]);
            rmax *= scale;
#pragma unroll
            for (int msk = 8; msk > 0; msk >>= 1)
                rmax = fmaxf(rmax, __shfl_xor_sync(0xffffffffu, rmax, msk));

            const float mn = fmaxf(m[i], rmax);
            const float corr = __expf(m[i] - mn);
            m[i] = mn;

            float p0 = __expf(s[i][0] * scale - mn);
            float p1 = __expf(s[i][1] * scale - mn);
            float p2 = __expf(s[i][2] * scale - mn);
            float p3 = __expf(s[i][3] * scale - mn);
            *(float4*)&Ps[ty * 4 + i][tx * 4] = make_float4(p0, p1, p2, p3);

            float rs = p0 + p1 + p2 + p3;
#pragma unroll
            for (int msk = 8; msk > 0; msk >>= 1)
                rs += __shfl_xor_sync(0xffffffffu, rs, msk);

            lsum[i] = lsum[i] * corr + rs;
#pragma unroll
            for (int j = 0; j < 4; j++) O[i][j] *= corr;
        }
        __syncthreads();

        // O += P @ V
#pragma unroll 8
        for (int jj = 0; jj < 64; jj++) {
            float4 v4 = *(const float4*)&Vs[jj][tx * 4];
#pragma unroll
            for (int i = 0; i < 4; i++) {
                const float p = Ps[ty * 4 + i][jj];
                O[i][0] += p * v4.x;
                O[i][1] += p * v4.y;
                O[i][2] += p * v4.z;
                O[i][3] += p * v4.w;
            }
        }
    }

    // write normalized output:  hout[(b*L + l)*C + h*D + d]
#pragma unroll
    for (int i = 0; i < 4; i++) {
        const float inv = 1.0f / lsum[i];
        float4 o = make_float4(O[i][0] * inv, O[i][1] * inv,
                               O[i][2] * inv, O[i][3] * inv);
        *(float4*)(hout + (size_t)(b * L_ + l0 + ty * 4 + i) * C_ + h * D_ + tx * 4) = o;
    }
}

// ---------------------------------------------------------------------------
// kernel_launch
// ---------------------------------------------------------------------------
extern "C" void kernel_launch(void* const* d_in, const int* in_sizes, int n_in,
                              void* d_out, int out_size)
{
    const float* x     = (const float*)d_in[0];
    const float* Wqkv  = (const float*)d_in[1];
    const float* bqkv  = (const float*)d_in[2];
    const float* qg    = (const float*)d_in[3];
    const float* kg    = (const float*)d_in[4];
    const float* Wout  = (const float*)d_in[5];
    const float* bout  = (const float*)d_in[6];
    float* out = (float*)d_out;

    float *qkv, *hbuf;
    cudaGetSymbolAddress((void**)&qkv, g_qkv);
    cudaGetSymbolAddress((void**)&hbuf, g_h);

    // 1) QKV projection: [8192,1024] @ [1024,3072] + bias
    {
        dim3 grid(3 * C_ / 128, M_ / 128);
        sgemm_bias_kernel<<<grid, 256>>>(x, Wqkv, bqkv, qkv, M_, 3 * C_, C_);
    }

    // 2) RMS norm on Q and K heads (in place)
    {
        const int nseg = M_ * 2 * H_;          // 262144 warps
        rmsnorm_kernel<<<nseg / 8, 256>>>(qkv, qg, kg);
    }

    // 3) Attention
    {
        const int smem = 4 * 64 * AP * sizeof(float);   // 69632 B
        cudaFuncSetAttribute(attn_kernel,
                             cudaFuncAttributeMaxDynamicSharedMemorySize, smem);
        dim3 grid(L_ / 64, H_, B_);
        attn_kernel<<<grid, 256, smem>>>(qkv, hbuf);
    }

    // 4) Output projection: [8192,1024] @ [1024,1024] + bias
    {
        dim3 grid(C_ / 128, M_ / 128);
        sgemm_bias_kernel<<<grid, 256>>>(hbuf, Wout, bout, out, M_, C_, C_);
    }
}

// round 2
// speedup vs baseline: 2.0687x; 2.0687x over previous
#include <cuda_runtime.h>
#include <math.h>
#include <stdint.h>

#define B_ 4
#define L_ 2048
#define C_ 1024
#define H_ 16
#define D_ 64
#define M_ (B_ * L_)   // 8192 rows

// Scratch buffers (static device globals; no runtime allocation allowed)
__device__ float g_qkv[(size_t)M_ * 3 * C_];   // [8192, 3072]
__device__ float g_h[(size_t)M_ * C_];         // [8192, 1024]

// ---------------------------------------------------------------------------
// helpers: tf32 convert + m16n8k8 tf32 mma
// ---------------------------------------------------------------------------
__device__ __forceinline__ uint32_t f2tf(float f) {
    uint32_t r;
    asm("cvt.rna.tf32.f32 %0, %1;" : "=r"(r) : "f"(f));
    return r;
}

__device__ __forceinline__ void mma_tf32(float c[4],
    uint32_t a0, uint32_t a1, uint32_t a2, uint32_t a3,
    uint32_t b0, uint32_t b1)
{
    asm volatile(
        "mma.sync.aligned.m16n8k8.row.col.f32.tf32.tf32.f32 "
        "{%0,%1,%2,%3}, {%4,%5,%6,%7}, {%8,%9}, {%0,%1,%2,%3};"
        : "+f"(c[0]), "+f"(c[1]), "+f"(c[2]), "+f"(c[3])
        : "r"(a0), "r"(a1), "r"(a2), "r"(a3), "r"(b0), "r"(b1));
}

// ---------------------------------------------------------------------------
// TF32 tensor-core SGEMM: C[M,N] = A[M,K] @ B[K,N] + bias[N]  (row-major)
// 128x128 tile, BK=16, 256 threads = 8 warps in 4(M) x 2(N), warp tile 32x64.
// As stored [m][k] pitch 20 (conflict-free A-frag loads),
// Bs stored [k][n] pitch 136 (conflict-free B-frag loads).
// Requires M%128==0, N%128==0, K%16==0.
// ---------------------------------------------------------------------------
#define GAP 20
#define GBP 136

__global__ __launch_bounds__(256) void gemm_tc_kernel(
    const float* __restrict__ A, const float* __restrict__ Bm,
    const float* __restrict__ bias, float* __restrict__ Cm,
    int M, int N, int K)
{
    __shared__ uint32_t As[128 * GAP];
    __shared__ uint32_t Bs[16 * GBP];

    const int tid  = threadIdx.x;
    const int warp = tid >> 5;
    const int lane = tid & 31;
    const int gid  = lane >> 2;
    const int t4   = lane & 3;

    const int wm = warp >> 1;         // 0..3
    const int wn = warp & 1;          // 0..1
    const int m0 = wm * 32;
    const int n0 = wn * 64;

    const int row0 = blockIdx.y * 128;
    const int col0 = blockIdx.x * 128;

    // loader indices
    const int a_row = tid >> 1;            // 0..127
    const int a_k   = (tid & 1) * 8;       // 0 or 8
    const int b_row = tid >> 4;            // 0..15
    const int b_col = (tid & 15) * 8;      // 0..120

    float acc[2][8][4];
#pragma unroll
    for (int mt = 0; mt < 2; mt++)
#pragma unroll
        for (int nt = 0; nt < 8; nt++)
#pragma unroll
            for (int i = 0; i < 4; i++) acc[mt][nt][i] = 0.0f;

    const float* Aptr = A + (size_t)(row0 + a_row) * K;

    for (int k0 = 0; k0 < K; k0 += 16) {
        // A tile: 2 x float4 per thread
        float4 av0 = *(const float4*)(Aptr + k0 + a_k);
        float4 av1 = *(const float4*)(Aptr + k0 + a_k + 4);
        {
            uint4 u0 = make_uint4(f2tf(av0.x), f2tf(av0.y), f2tf(av0.z), f2tf(av0.w));
            uint4 u1 = make_uint4(f2tf(av1.x), f2tf(av1.y), f2tf(av1.z), f2tf(av1.w));
            *(uint4*)&As[a_row * GAP + a_k]     = u0;
            *(uint4*)&As[a_row * GAP + a_k + 4] = u1;
        }
        // B tile: 2 x float4 per thread
        float4 bv0 = *(const float4*)(Bm + (size_t)(k0 + b_row) * N + col0 + b_col);
        float4 bv1 = *(const float4*)(Bm + (size_t)(k0 + b_row) * N + col0 + b_col + 4);
        {
            uint4 u0 = make_uint4(f2tf(bv0.x), f2tf(bv0.y), f2tf(bv0.z), f2tf(bv0.w));
            uint4 u1 = make_uint4(f2tf(bv1.x), f2tf(bv1.y), f2tf(bv1.z), f2tf(bv1.w));
            *(uint4*)&Bs[b_row * GBP + b_col]     = u0;
            *(uint4*)&Bs[b_row * GBP + b_col + 4] = u1;
        }
        __syncthreads();

#pragma unroll
        for (int ks = 0; ks < 16; ks += 8) {
            uint32_t af[2][4];
#pragma unroll
            for (int mt = 0; mt < 2; mt++) {
                const int mbase = m0 + mt * 16;
                af[mt][0] = As[(mbase + gid)     * GAP + ks + t4];
                af[mt][1] = As[(mbase + gid + 8) * GAP + ks + t4];
                af[mt][2] = As[(mbase + gid)     * GAP + ks + t4 + 4];
                af[mt][3] = As[(mbase + gid + 8) * GAP + ks + t4 + 4];
            }
#pragma unroll
            for (int nt = 0; nt < 8; nt++) {
                uint32_t b0 = Bs[(ks + t4)     * GBP + n0 + nt * 8 + gid];
                uint32_t b1 = Bs[(ks + t4 + 4) * GBP + n0 + nt * 8 + gid];
                mma_tf32(acc[0][nt], af[0][0], af[0][1], af[0][2], af[0][3], b0, b1);
                mma_tf32(acc[1][nt], af[1][0], af[1][1], af[1][2], af[1][3], b0, b1);
            }
        }
        __syncthreads();
    }

    // epilogue with bias
#pragma unroll
    for (int mt = 0; mt < 2; mt++) {
        const int r0 = row0 + m0 + mt * 16 + gid;
#pragma unroll
        for (int nt = 0; nt < 8; nt++) {
            const int c = col0 + n0 + nt * 8 + t4 * 2;
            float bx = bias[c], by = bias[c + 1];
            *(float2*)(Cm + (size_t)r0 * N + c) =
                make_float2(acc[mt][nt][0] + bx, acc[mt][nt][1] + by);
            *(float2*)(Cm + (size_t)(r0 + 8) * N + c) =
                make_float2(acc[mt][nt][2] + bx, acc[mt][nt][3] + by);
        }
    }
}

// ---------------------------------------------------------------------------
// Per-head RMS norm on Q and K slices of qkv, in place (unchanged).
// ---------------------------------------------------------------------------
__global__ __launch_bounds__(256) void rmsnorm_kernel(
    float* __restrict__ qkv,
    const float* __restrict__ q_gamma, const float* __restrict__ k_gamma)
{
    const int warp = threadIdx.x >> 5;
    const int lane = threadIdx.x & 31;
    const int seg = blockIdx.x * 8 + warp;

    const int head = seg % H_;
    const int part = (seg / H_) & 1;
    const int row  = seg / (H_ * 2);

    float* ptr = qkv + ((size_t)row * 3 + part) * C_ + head * D_;
    float2 v = *(float2*)(ptr + lane * 2);
    float ss = v.x * v.x + v.y * v.y;
#pragma unroll
    for (int m = 16; m > 0; m >>= 1) ss += __shfl_xor_sync(0xffffffffu, ss, m);

    const float n = sqrtf(ss);
    const float scale = 8.0f / fmaxf(n, 1e-12f);
    const float* gamma = part ? k_gamma : q_gamma;
    float2 g = *(const float2*)(gamma + head * D_ + lane * 2);
    v.x *= scale * g.x;
    v.y *= scale * g.y;
    *(float2*)(ptr + lane * 2) = v;
}

// ---------------------------------------------------------------------------
// Flash attention with TF32 tensor cores.
// CTA = (b, h, 64-row Q tile). 128 threads = 4 warps; warp w owns Q rows
// w*16..w*16+15. Per 64-key tile: S = Q K^T via mma (Q frags in registers),
// online softmax on S fragments, P bounced through per-warp smem (tf32),
// O += P V via mma.
// Smem (uint32/tf32): Qs pitch 84, Ks pitch 84, Vs pitch 72, Ps pitch 84.
// ---------------------------------------------------------------------------
#define QP 84
#define KP 84
#define VP 72
#define PP 84
#define ATT_SMEM ((QP + KP + VP + PP) * 64 * 4)   // 82944 bytes

__global__ __launch_bounds__(128) void attn_tc_kernel(
    const float* __restrict__ qkv, float* __restrict__ hout)
{
    extern __shared__ uint32_t sm[];
    uint32_t* Qs = sm;
    uint32_t* Ks = Qs + 64 * QP;
    uint32_t* Vs = Ks + 64 * KP;
    uint32_t* Ps = Vs + 64 * VP;

    const int tid  = threadIdx.x;
    const int warp = tid >> 5;
    const int lane = tid & 31;
    const int gid  = lane >> 2;
    const int t4   = lane & 3;

    const int b  = blockIdx.z;
    const int h  = blockIdx.y;
    const int l0 = blockIdx.x * 64;

    // tile loader mapping: 128 threads cover 64 rows x 64 cols, 32 per thread
    const int lr = tid >> 1;            // 0..63
    const int lc = (tid & 1) * 32;      // 0 or 32

    // ---- load Q tile (tf32) ----
    {
        const float* src = qkv + (((size_t)(b * L_ + l0 + lr) * 3 + 0) * C_) + h * D_;
#pragma unroll
        for (int u = 0; u < 8; u++) {
            float4 t = *(const float4*)(src + lc + u * 4);
            uint4 uq = make_uint4(f2tf(t.x), f2tf(t.y), f2tf(t.z), f2tf(t.w));
            *(uint4*)&Qs[lr * QP + lc + u * 4] = uq;
        }
    }
    __syncthreads();

    // ---- Q fragments to registers (invariant across key tiles) ----
    uint32_t qf[8][4];
    {
        const int mbase = warp * 16;
#pragma unroll
        for (int ks = 0; ks < 8; ks++) {
            qf[ks][0] = Qs[(mbase + gid)     * QP + ks * 8 + t4];
            qf[ks][1] = Qs[(mbase + gid + 8) * QP + ks * 8 + t4];
            qf[ks][2] = Qs[(mbase + gid)     * QP + ks * 8 + t4 + 4];
            qf[ks][3] = Qs[(mbase + gid + 8) * QP + ks * 8 + t4 + 4];
        }
    }

    float o[8][4];
#pragma unroll
    for (int nt = 0; nt < 8; nt++)
#pragma unroll
        for (int i = 0; i < 4; i++) o[nt][i] = 0.0f;

    float mrow0 = -1e30f, mrow1 = -1e30f;
    float lrow0 = 0.0f,   lrow1 = 0.0f;
    const float scale = 0.125f;   // 1/sqrt(64)

    for (int n0 = 0; n0 < L_; n0 += 64) {
        __syncthreads();   // K/V consumed by all warps in previous iter

        // ---- load K, V tiles (tf32) ----
        {
            const float* ksrc = qkv + (((size_t)(b * L_ + n0 + lr) * 3 + 1) * C_) + h * D_;
            const float* vsrc = qkv + (((size_t)(b * L_ + n0 + lr) * 3 + 2) * C_) + h * D_;
#pragma unroll
            for (int u = 0; u < 8; u++) {
                float4 tk = *(const float4*)(ksrc + lc + u * 4);
                float4 tv = *(const float4*)(vsrc + lc + u * 4);
                *(uint4*)&Ks[lr * KP + lc + u * 4] =
                    make_uint4(f2tf(tk.x), f2tf(tk.y), f2tf(tk.z), f2tf(tk.w));
                *(uint4*)&Vs[lr * VP + lc + u * 4] =
                    make_uint4(f2tf(tv.x), f2tf(tv.y), f2tf(tv.z), f2tf(tv.w));
            }
        }
        __syncthreads();

        // ---- S = Q K^T (64-key tile), per-warp 16x64 ----
        float s[8][4];
#pragma unroll
        for (int nt = 0; nt < 8; nt++)
#pragma unroll
            for (int i = 0; i < 4; i++) s[nt][i] = 0.0f;

#pragma unroll
        for (int ks = 0; ks < 8; ks++) {
#pragma unroll
            for (int nt = 0; nt < 8; nt++) {
                uint32_t b0 = Ks[(nt * 8 + gid) * KP + ks * 8 + t4];
                uint32_t b1 = Ks[(nt * 8 + gid) * KP + ks * 8 + t4 + 4];
                mma_tf32(s[nt], qf[ks][0], qf[ks][1], qf[ks][2], qf[ks][3], b0, b1);
            }
        }

        // ---- online softmax (rows gid / gid+8 within warp's 16) ----
        float rmax0 = -1e30f, rmax1 = -1e30f;
#pragma unroll
        for (int nt = 0; nt < 8; nt++) {
            rmax0 = fmaxf(rmax0, fmaxf(s[nt][0], s[nt][1]));
            rmax1 = fmaxf(rmax1, fmaxf(s[nt][2], s[nt][3]));
        }
#pragma unroll
        for (int msk = 1; msk <= 2; msk <<= 1) {
            rmax0 = fmaxf(rmax0, __shfl_xor_sync(0xffffffffu, rmax0, msk));
            rmax1 = fmaxf(rmax1, __shfl_xor_sync(0xffffffffu, rmax1, msk));
        }

        const float mn0 = fmaxf(mrow0, rmax0 * scale);
        const float mn1 = fmaxf(mrow1, rmax1 * scale);
        const float corr0 = __expf(mrow0 - mn0);
        const float corr1 = __expf(mrow1 - mn1);
        mrow0 = mn0; mrow1 = mn1;

        const int prow0 = warp * 16 + gid;
        float rs0 = 0.0f, rs1 = 0.0f;
#pragma unroll
        for (int nt = 0; nt < 8; nt++) {
            float p0 = __expf(s[nt][0] * scale - mn0);
            float p1 = __expf(s[nt][1] * scale - mn0);
            float p2 = __expf(s[nt][2] * scale - mn1);
            float p3 = __expf(s[nt][3] * scale - mn1);
            rs0 += p0 + p1;
            rs1 += p2 + p3;
            const int cc = nt * 8 + 2 * t4;
            Ps[prow0 * PP + cc]           = f2tf(p0);
            Ps[prow0 * PP + cc + 1]       = f2tf(p1);
            Ps[(prow0 + 8) * PP + cc]     = f2tf(p2);
            Ps[(prow0 + 8) * PP + cc + 1] = f2tf(p3);
        }
#pragma unroll
        for (int msk = 1; msk <= 2; msk <<= 1) {
            rs0 += __shfl_xor_sync(0xffffffffu, rs0, msk);
            rs1 += __shfl_xor_sync(0xffffffffu, rs1, msk);
        }
        lrow0 = lrow0 * corr0 + rs0;
        lrow1 = lrow1 * corr1 + rs1;

#pragma unroll
        for (int nt = 0; nt < 8; nt++) {
            o[nt][0] *= corr0; o[nt][1] *= corr0;
            o[nt][2] *= corr1; o[nt][3] *= corr1;
        }
        __syncwarp();   // Ps visible within warp

        // ---- O += P V ----
#pragma unroll
        for (int ks = 0; ks < 8; ks++) {
            uint32_t pf0 = Ps[(warp * 16 + gid)     * PP + ks * 8 + t4];
            uint32_t pf1 = Ps[(warp * 16 + gid + 8) * PP + ks * 8 + t4];
            uint32_t pf2 = Ps[(warp * 16 + gid)     * PP + ks * 8 + t4 + 4];
            uint32_t pf3 = Ps[(warp * 16 + gid + 8) * PP + ks * 8 + t4 + 4];
#pragma unroll
            for (int nt = 0; nt < 8; nt++) {
                uint32_t b0 = Vs[(ks * 8 + t4)     * VP + nt * 8 + gid];
                uint32_t b1 = Vs[(ks * 8 + t4 + 4) * VP + nt * 8 + gid];
                mma_tf32(o[nt], pf0, pf1, pf2, pf3, b0, b1);
            }
        }
    }

    // ---- write normalized output ----
    const float inv0 = 1.0f / lrow0;
    const float inv1 = 1.0f / lrow1;
    const int r0 = b * L_ + l0 + warp * 16 + gid;
#pragma unroll
    for (int nt = 0; nt < 8; nt++) {
        const int c = h * D_ + nt * 8 + 2 * t4;
        *(float2*)(hout + (size_t)r0 * C_ + c) =
            make_float2(o[nt][0] * inv0, o[nt][1] * inv0);
        *(float2*)(hout + (size_t)(r0 + 8) * C_ + c) =
            make_float2(o[nt][2] * inv1, o[nt][3] * inv1);
    }
}

// ---------------------------------------------------------------------------
// kernel_launch
// ---------------------------------------------------------------------------
extern "C" void kernel_launch(void* const* d_in, const int* in_sizes, int n_in,
                              void* d_out, int out_size)
{
    const float* x     = (const float*)d_in[0];
    const float* Wqkv  = (const float*)d_in[1];
    const float* bqkv  = (const float*)d_in[2];
    const float* qg    = (const float*)d_in[3];
    const float* kg    = (const float*)d_in[4];
    const float* Wout  = (const float*)d_in[5];
    const float* bout  = (const float*)d_in[6];
    float* out = (float*)d_out;

    float *qkv, *hbuf;
    cudaGetSymbolAddress((void**)&qkv, g_qkv);
    cudaGetSymbolAddress((void**)&hbuf, g_h);

    // 1) QKV projection
    {
        dim3 grid(3 * C_ / 128, M_ / 128);
        gemm_tc_kernel<<<grid, 256>>>(x, Wqkv, bqkv, qkv, M_, 3 * C_, C_);
    }

    // 2) RMS norm on Q and K heads (in place)
    {
        const int nseg = M_ * 2 * H_;
        rmsnorm_kernel<<<nseg / 8, 256>>>(qkv, qg, kg);
    }

    // 3) Attention
    {
        static int attr_set = 0;
        if (!attr_set) {
            cudaFuncSetAttribute(attn_tc_kernel,
                                 cudaFuncAttributeMaxDynamicSharedMemorySize,
                                 ATT_SMEM);
            attr_set = 1;
        }
        dim3 grid(L_ / 64, H_, B_);
        attn_tc_kernel<<<grid, 128, ATT_SMEM>>>(qkv, hbuf);
    }

    // 4) Output projection
    {
        dim3 grid(C_ / 128, M_ / 128);
        gemm_tc_kernel<<<grid, 256>>>(hbuf, Wout, bout, out, M_, C_, C_);
    }
}